// round 15
// baseline (speedup 1.0000x reference)
#include <cuda_runtime.h>
#include <cuda_bf16.h>
#include <math.h>
#include <stdint.h>

// ---------------------------------------------------------------------------
// Shapes (fixed): B=2, L=1024, d_model=1024, d_state=16, d_conv=4, d_inner=2048
// ---------------------------------------------------------------------------
#define BATCH    2
#define LSEQ     1024
#define DMODEL   1024
#define DSTATE   16
#define DCONV    4
#define DINNER   2048
#define ROWS     (BATCH * LSEQ)
#define NSEG     64
#define SEGLEN   16

// ---------------------------------------------------------------------------
// Scratch (device globals; no allocation allowed)
// ---------------------------------------------------------------------------
__device__ __nv_bfloat16 g_xn_h[ROWS * DMODEL];
__device__ __nv_bfloat16 g_wi_h[2 * DINNER * DMODEL];
__device__ __nv_bfloat16 g_wd_h[DINNER * DINNER];
__device__ __nv_bfloat16 g_wo_h[DMODEL * DINNER];
__device__ __nv_bfloat16 g_xc_h[ROWS * DINNER];
__device__ __nv_bfloat16 g_y_h [ROWS * DINNER];
__device__ float g_xz   [ROWS * 2 * DINNER];
__device__ float g_bc   [ROWS * 2 * DSTATE];    // interleaved [t][s][{B,C}]
__device__ float g_delta[ROWS * DINNER];
__device__ float g_out  [ROWS * DMODEL];

// ---------------------------------------------------------------------------
// PTX helpers (plain sm_80+ features only)
// ---------------------------------------------------------------------------
__device__ __forceinline__ uint32_t smem_to_u32(const void* p) {
    uint32_t a;
    asm("{ .reg .u64 t; cvta.to.shared.u64 t, %1; cvt.u32.u64 %0, t; }" : "=r"(a) : "l"(p));
    return a;
}
#define CP_ASYNC16(dst, src) \
    asm volatile("cp.async.cg.shared.global [%0], [%1], 16;" :: "r"(dst), "l"(src))
#define CP_COMMIT() asm volatile("cp.async.commit_group;" ::: "memory")
#define CP_WAIT(n)  asm volatile("cp.async.wait_group %0;" :: "n"(n) : "memory")

__device__ __forceinline__ void ldsm_x4(uint32_t* r, uint32_t addr) {
    asm volatile("ldmatrix.sync.aligned.m8n8.x4.shared.b16 {%0,%1,%2,%3}, [%4];"
        : "=r"(r[0]), "=r"(r[1]), "=r"(r[2]), "=r"(r[3]) : "r"(addr));
}
__device__ __forceinline__ void mma_bf16(float* c, const uint32_t* a, const uint32_t* b) {
    asm volatile(
        "mma.sync.aligned.m16n8k16.row.col.f32.bf16.bf16.f32 "
        "{%0,%1,%2,%3}, {%4,%5,%6,%7}, {%8,%9}, {%0,%1,%2,%3};"
        : "+f"(c[0]), "+f"(c[1]), "+f"(c[2]), "+f"(c[3])
        : "r"(a[0]), "r"(a[1]), "r"(a[2]), "r"(a[3]), "r"(b[0]), "r"(b[1]));
}

__device__ __forceinline__ float warp_sum32(float v) {
    #pragma unroll
    for (int m = 16; m > 0; m >>= 1) v += __shfl_xor_sync(0xffffffffu, v, m);
    return v;
}

// ---------------------------------------------------------------------------
// Fused: input LN (blocks 0..2047) + weight converts + g_bc bias seeding
// ---------------------------------------------------------------------------
#define WI_N4 (2 * DINNER * DMODEL / 4)
#define WD_N4 (DINNER * DINNER / 4)
#define WO_N4 (DMODEL * DINNER / 4)
#define CVT_N4 (WI_N4 + WD_N4 + WO_N4)
#define CVT_BLOCKS ((CVT_N4 + 255) / 256)
#define BC_BLOCKS  (ROWS * 2 * DSTATE / 256)

__global__ void ln_cvt_kernel(const float* __restrict__ X,
                              const float* __restrict__ alpha,
                              const float* __restrict__ beta,
                              __nv_bfloat16* __restrict__ Yh,
                              const float* __restrict__ Wi,
                              const float* __restrict__ Wd,
                              const float* __restrict__ Wo,
                              const float* __restrict__ xp_bias) {
    int tid = threadIdx.x;
    if (blockIdx.x >= ROWS + CVT_BLOCKS) {
        int i = (blockIdx.x - ROWS - CVT_BLOCKS) * 256 + tid;
        int p = i & 31;
        g_bc[i] = xp_bias[(p & 1) * 16 + (p >> 1)];
        return;
    }
    if (blockIdx.x >= ROWS) {
        long i = (long)(blockIdx.x - ROWS) * 256 + tid;
        if (i >= CVT_N4) return;
        const float* src; __nv_bfloat16* dst; long idx;
        if (i < WI_N4)              { src = Wi; dst = g_wi_h; idx = i; }
        else if (i < WI_N4 + WD_N4) { src = Wd; dst = g_wd_h; idx = i - WI_N4; }
        else                        { src = Wo; dst = g_wo_h; idx = i - WI_N4 - WD_N4; }
        float4 v = *(const float4*)(src + idx * 4);
        __nv_bfloat16 h[4] = { __float2bfloat16(v.x), __float2bfloat16(v.y),
                               __float2bfloat16(v.z), __float2bfloat16(v.w) };
        *(uint2*)(dst + idx * 4) = *(uint2*)h;
        return;
    }
    __shared__ float sh[2][8];
    int row = blockIdx.x;
    const float* xr = X + (long)row * DMODEL;
    float4 xv = *(const float4*)(xr + tid * 4);
    float s  = xv.x + xv.y + xv.z + xv.w;
    float ss = xv.x*xv.x + xv.y*xv.y + xv.z*xv.z + xv.w*xv.w;
    s = warp_sum32(s); ss = warp_sum32(ss);
    if ((tid & 31) == 0) { sh[0][tid >> 5] = s; sh[1][tid >> 5] = ss; }
    __syncthreads();
    float S = 0.f, SS = 0.f;
    #pragma unroll
    for (int w = 0; w < 8; ++w) { S += sh[0][w]; SS += sh[1][w]; }
    float mean = S * (1.0f / (float)DMODEL);
    float var  = fmaxf((SS - (float)DMODEL * mean * mean) * (1.0f / (float)(DMODEL - 1)), 0.f);
    float inv  = 1.0f / (sqrtf(var) + 1e-6f);
    float4 av = *(const float4*)(alpha + tid * 4);
    float4 bv = *(const float4*)(beta  + tid * 4);
    __nv_bfloat16 h[4];
    h[0] = __float2bfloat16(av.x * (xv.x - mean) * inv + bv.x);
    h[1] = __float2bfloat16(av.y * (xv.y - mean) * inv + bv.y);
    h[2] = __float2bfloat16(av.z * (xv.z - mean) * inv + bv.z);
    h[3] = __float2bfloat16(av.w * (xv.w - mean) * inv + bv.w);
    *(uint2*)(Yh + (long)row * DMODEL + tid * 4) = *(uint2*)h;
}

// ---------------------------------------------------------------------------
// Final layernorm (fp32 out)
// ---------------------------------------------------------------------------
__global__ void ln_out_kernel(const float* __restrict__ X,
                              const float* __restrict__ alpha,
                              const float* __restrict__ beta,
                              float* __restrict__ Y) {
    __shared__ float sh[2][8];
    int row = blockIdx.x;
    int tid = threadIdx.x;
    const float* xr = X + (long)row * DMODEL;
    float4 xv = *(const float4*)(xr + tid * 4);
    float s  = xv.x + xv.y + xv.z + xv.w;
    float ss = xv.x*xv.x + xv.y*xv.y + xv.z*xv.z + xv.w*xv.w;
    s = warp_sum32(s); ss = warp_sum32(ss);
    if ((tid & 31) == 0) { sh[0][tid >> 5] = s; sh[1][tid >> 5] = ss; }
    __syncthreads();
    float S = 0.f, SS = 0.f;
    #pragma unroll
    for (int w = 0; w < 8; ++w) { S += sh[0][w]; SS += sh[1][w]; }
    float mean = S * (1.0f / (float)DMODEL);
    float var  = fmaxf((SS - (float)DMODEL * mean * mean) * (1.0f / (float)(DMODEL - 1)), 0.f);
    float inv  = 1.0f / (sqrtf(var) + 1e-6f);
    float4 av = *(const float4*)(alpha + tid * 4);
    float4 bv = *(const float4*)(beta  + tid * 4);
    float4 o;
    o.x = av.x * (xv.x - mean) * inv + bv.x;
    o.y = av.y * (xv.y - mean) * inv + bv.y;
    o.z = av.z * (xv.z - mean) * inv + bv.z;
    o.w = av.w * (xv.w - mean) * inv + bv.w;
    *(float4*)(Y + (long)row * DMODEL + tid * 4) = o;
}

// ---------------------------------------------------------------------------
// GEMM epilogues
// ---------------------------------------------------------------------------
#define EPI_BIAS     0
#define EPI_SOFTPLUS 1
#define EPI_RESID    2
__device__ __forceinline__ float epi_apply(int EPI, float t, float r) {
    if (EPI == EPI_SOFTPLUS) {
        float sp = fmaxf(t, 0.f) + log1pf(expf(-fabsf(t)));
        t = fminf(fmaxf(sp, 1e-4f), 10.0f);
    } else if (EPI == EPI_RESID) {
        t += r;
    }
    return t;
}

// ---------------------------------------------------------------------------
// gemm_hmma: block 128x128, 8 warps, warp tile 64x32, BK=32, 4-stage, 2 CTA/SM
// ---------------------------------------------------------------------------
#define ROWB      80
#define ARR_SZ    (128 * ROWB)
#define STAGE_SZ  (2 * ARR_SZ)
#define NSTAGE    4
#define GEMM_SMEM (NSTAGE * STAGE_SZ)

template<int EPI>
__global__ __launch_bounds__(256, 2)
void gemm_hmma(const __nv_bfloat16* __restrict__ A, const __nv_bfloat16* __restrict__ B,
               const float* __restrict__ bias, const float* __restrict__ resid,
               float* __restrict__ C, int M, int N, int K) {
    extern __shared__ char smem[];
    uint32_t sb = smem_to_u32(smem);
    int tid  = threadIdx.x;
    int lane = tid & 31;
    int wid  = tid >> 5;
    int wm   = wid & 1;
    int wn   = wid >> 1;
    int bm = blockIdx.y * 128, bn = blockIdx.x * 128;

    const __nv_bfloat16* srcs[2] = { A + (long)bm * K, B + (long)bn * K };

    int s_arr[4], s_row[4], s_c[4];
    #pragma unroll
    for (int i = 0; i < 4; ++i) {
        int id = tid + i * 256;
        s_arr[i] = id >> 9;
        int rem = id & 511;
        s_row[i] = rem >> 2;
        s_c[i]   = rem & 3;
    }

    auto load_stage = [&](int kt, int buf) {
        #pragma unroll
        for (int i = 0; i < 4; ++i) {
            uint32_t dst = sb + buf * STAGE_SZ + s_arr[i] * ARR_SZ
                         + s_row[i] * ROWB + s_c[i] * 16;
            const __nv_bfloat16* src = srcs[s_arr[i]] + (long)s_row[i] * K
                                     + kt * 32 + s_c[i] * 8;
            CP_ASYNC16(dst, src);
        }
        CP_COMMIT();
    };

    float c[4][4][4];
    #pragma unroll
    for (int mt = 0; mt < 4; ++mt)
        #pragma unroll
        for (int nj = 0; nj < 4; ++nj)
            #pragma unroll
            for (int r = 0; r < 4; ++r) c[mt][nj][r] = 0.f;

    int a_row = wm * 64 + (lane & 15);
    int a_kb  = (lane >> 4) << 4;
    int b_row = wn * 32 + ((lane >> 4) << 3) + (lane & 7);
    int b_kb  = ((lane >> 3) & 1) << 4;

    auto load_frags = [&](uint32_t base, int ks, uint32_t a[4][4], uint32_t b[4][2]) {
        uint32_t kboff = ks * 32;
        #pragma unroll
        for (int mt = 0; mt < 4; ++mt) {
            uint32_t off = (uint32_t)((a_row + mt * 16) * ROWB) + a_kb + kboff;
            ldsm_x4(a[mt], base + off);
        }
        #pragma unroll
        for (int nt = 0; nt < 2; ++nt) {
            uint32_t off = (uint32_t)((b_row + nt * 16) * ROWB) + b_kb + kboff;
            uint32_t t0[4];
            ldsm_x4(t0, base + ARR_SZ + off);
            b[nt*2][0]   = t0[0]; b[nt*2][1]   = t0[1];
            b[nt*2+1][0] = t0[2]; b[nt*2+1][1] = t0[3];
        }
    };
    auto do_mmas = [&](uint32_t a[4][4], uint32_t b[4][2]) {
        #pragma unroll
        for (int mt = 0; mt < 4; ++mt)
            #pragma unroll
            for (int nj = 0; nj < 4; ++nj)
                mma_bf16(c[mt][nj], a[mt], b[nj]);
    };

    const int KT = K >> 5;
    load_stage(0, 0);
    load_stage(1, 1);
    load_stage(2, 2);
    int buf = 0;
    for (int kt = 0; kt < KT; ++kt) {
        if (kt + 3 < KT) {
            int nb = buf + 3; if (nb >= NSTAGE) nb -= NSTAGE;
            load_stage(kt + 3, nb);
            CP_WAIT(3);
        } else if (kt + 2 < KT) { CP_WAIT(2); }
        else if (kt + 1 < KT)   { CP_WAIT(1); }
        else                    { CP_WAIT(0); }
        __syncthreads();

        uint32_t base = sb + buf * STAGE_SZ;
        uint32_t a0[4][4], b0[4][2], a1[4][4], b1[4][2];
        load_frags(base, 0, a0, b0);
        load_frags(base, 1, a1, b1);
        do_mmas(a0, b0);
        do_mmas(a1, b1);
        __syncthreads();
        if (++buf == NSTAGE) buf = 0;
    }

    #pragma unroll
    for (int mt = 0; mt < 4; ++mt) {
        #pragma unroll
        for (int nj = 0; nj < 4; ++nj) {
            int row0 = bm + wm * 64 + mt * 16 + (lane >> 2);
            int col  = bn + wn * 32 + nj * 8 + (lane & 3) * 2;
            float b0 = bias[col], b1 = bias[col + 1];
            long p0 = (long)row0 * N + col, p1 = (long)(row0 + 8) * N + col;
            float r0 = (EPI == EPI_RESID) ? resid[p0]     : 0.f;
            float r1 = (EPI == EPI_RESID) ? resid[p0 + 1] : 0.f;
            float r2 = (EPI == EPI_RESID) ? resid[p1]     : 0.f;
            float r3 = (EPI == EPI_RESID) ? resid[p1 + 1] : 0.f;
            float v0 = epi_apply(EPI, c[mt][nj][0] + b0, r0);
            float v1 = epi_apply(EPI, c[mt][nj][1] + b1, r1);
            float v2 = epi_apply(EPI, c[mt][nj][2] + b0, r2);
            float v3 = epi_apply(EPI, c[mt][nj][3] + b1, r3);
            *(float2*)(C + p0) = make_float2(v0, v1);
            *(float2*)(C + p1) = make_float2(v2, v3);
        }
    }
}

// ---------------------------------------------------------------------------
// x_proj fused with causal conv(4)+SiLU. Grid (8 kchunks, 64 rowtiles).
// Computes conv from g_xz, writes bf16 xc, accumulates BC with atomics.
// ---------------------------------------------------------------------------
#define XP_KCHUNK 256
__global__ __launch_bounds__(256)
void xproj_conv_kernel(const float* __restrict__ W,
                       const float* __restrict__ conv_w,
                       const float* __restrict__ conv_b) {
    __shared__ float Xs[32][65];
    __shared__ float Ws[32][65];
    __shared__ float Cw[XP_KCHUNK][4];
    __shared__ float Cb[XP_KCHUNK];
    int tid = threadIdx.x;
    int kbase = blockIdx.x * XP_KCHUNK;
    int row0  = blockIdx.y * 32;
    if (tid < XP_KCHUNK) {
        float4 w = *(const float4*)(conv_w + (long)(kbase + tid) * 4);
        Cw[tid][0] = w.x; Cw[tid][1] = w.y; Cw[tid][2] = w.z; Cw[tid][3] = w.w;
        Cb[tid] = conv_b[kbase + tid];
    }
    __syncthreads();

    int rg = (tid >> 5) * 4;
    int n  = tid & 31;
    float acc[4] = {0.f, 0.f, 0.f, 0.f};
    for (int k0 = kbase; k0 < kbase + XP_KCHUNK; k0 += 64) {
        #pragma unroll
        for (int i = 0; i < 2; ++i) {
            int id = tid * 2 + i;
            int r = id >> 4, c4 = (id & 15) * 4;
            int row = row0 + r;
            int t = row & (LSEQ - 1);
            const float* xp = g_xz + (long)row * (2 * DINNER) + k0 + c4;
            float4 zf = make_float4(0.f, 0.f, 0.f, 0.f);
            float4 v3 = *(const float4*)xp;
            float4 v2 = (t >= 1) ? *(const float4*)(xp - 1 * 2 * DINNER) : zf;
            float4 v1 = (t >= 2) ? *(const float4*)(xp - 2 * 2 * DINNER) : zf;
            float4 v0 = (t >= 3) ? *(const float4*)(xp - 3 * 2 * DINNER) : zf;
            int ci = k0 + c4 - kbase;
            float o[4];
            o[0] = Cb[ci+0] + v0.x*Cw[ci+0][0] + v1.x*Cw[ci+0][1] + v2.x*Cw[ci+0][2] + v3.x*Cw[ci+0][3];
            o[1] = Cb[ci+1] + v0.y*Cw[ci+1][0] + v1.y*Cw[ci+1][1] + v2.y*Cw[ci+1][2] + v3.y*Cw[ci+1][3];
            o[2] = Cb[ci+2] + v0.z*Cw[ci+2][0] + v1.z*Cw[ci+2][1] + v2.z*Cw[ci+2][2] + v3.z*Cw[ci+2][3];
            o[3] = Cb[ci+3] + v0.w*Cw[ci+3][0] + v1.w*Cw[ci+3][1] + v2.w*Cw[ci+3][2] + v3.w*Cw[ci+3][3];
            __nv_bfloat16 hh[4];
            #pragma unroll
            for (int k = 0; k < 4; ++k) {
                o[k] = o[k] / (1.0f + expf(-o[k]));     // silu
                Xs[r][c4 + k] = o[k];
                hh[k] = __float2bfloat16(o[k]);
            }
            *(uint2*)(g_xc_h + (long)row * DINNER + k0 + c4) = *(uint2*)hh;
            float4 wv = *(const float4*)(W + (long)r * DINNER + k0 + c4);
            Ws[r][c4] = wv.x; Ws[r][c4+1] = wv.y; Ws[r][c4+2] = wv.z; Ws[r][c4+3] = wv.w;
        }
        __syncthreads();
        #pragma unroll
        for (int kk = 0; kk < 64; ++kk) {
            float w = Ws[n][kk];
            #pragma unroll
            for (int i = 0; i < 4; ++i) acc[i] = fmaf(Xs[rg + i][kk], w, acc[i]);
        }
        __syncthreads();
    }
    int off = (n & 15) * 2 + (n >> 4);
    #pragma unroll
    for (int i = 0; i < 4; ++i)
        atomicAdd(&g_bc[(long)(row0 + rg + i) * 32 + off], acc[i]);
}

// ---------------------------------------------------------------------------
// Fused chunked selective scan: all 3 phases in one kernel.
// Block = 8 (b,c) pairs, 512 threads (16 warps). Smem holds ap/hd (hs reuses
// ap slots). Phase1: warp w does segments 4w..4w+3 for its 8 channels.
// Phase2: warps 0-3 do the 64-step serial propagation. Phase3: re-run.
// ---------------------------------------------------------------------------
#define CH_STRIDE 1032                      // 64*16 + 8 pad (floats)
#define SC_SMEM  (2 * 8 * CH_STRIDE * 4)    // 66048 B

__global__ __launch_bounds__(512, 2)
void scan_fused(const float* __restrict__ A_log, const float* __restrict__ Dvec) {
    extern __shared__ float sm[];
    float* s_ap = sm;                       // becomes hs after phase2
    float* s_hd = sm + 8 * CH_STRIDE;

    int tid  = threadIdx.x;
    int wid  = tid >> 5;                    // 0..15
    int lane = tid & 31;
    int chl  = lane >> 2;
    int sg   = lane & 3;
    int s0   = sg * 4;
    int pair = blockIdx.x * 8 + chl;
    int b = pair >> 11;
    int c = pair & (DINNER - 1);

    float a[4];
    #pragma unroll
    for (int k = 0; k < 4; ++k) a[k] = -expf(A_log[c * DSTATE + s0 + k]);
    float Dc = Dvec[c];

    const float* dl  = g_delta + (long)b * LSEQ * DINNER + c;
    const __nv_bfloat16* xcb = g_xc_h + (long)b * LSEQ * DINNER + c;
    const float* bcb = g_bc + (long)b * LSEQ * 32 + s0 * 2;
    const float* zb  = g_xz + (long)b * LSEQ * 2 * DINNER + DINNER + c;
    __nv_bfloat16* yb = g_y_h + (long)b * LSEQ * DINNER + c;

    // ---- phase 1: per-segment transfer + driven response ----
    for (int sgm = wid * 4; sgm < wid * 4 + 4; ++sgm) {
        float h[4] = {0.f, 0.f, 0.f, 0.f};
        float ap[4] = {1.f, 1.f, 1.f, 1.f};
        int tb = sgm * SEGLEN;
        #pragma unroll
        for (int j = 0; j < SEGLEN; ++j) {
            int t = tb + j;
            float  d   = dl [(long)t * DINNER];
            float  xv  = __bfloat162float(xcb[(long)t * DINNER]);
            float4 bc0 = *(const float4*)(bcb + t * 32);
            float4 bc1 = *(const float4*)(bcb + t * 32 + 4);
            float dx = d * xv;
            float da0 = __expf(fmaxf(d * a[0], -10.f));
            float da1 = __expf(fmaxf(d * a[1], -10.f));
            float da2 = __expf(fmaxf(d * a[2], -10.f));
            float da3 = __expf(fmaxf(d * a[3], -10.f));
            h[0] = fmaf(da0, h[0], dx * bc0.x);  ap[0] *= da0;
            h[1] = fmaf(da1, h[1], dx * bc0.z);  ap[1] *= da1;
            h[2] = fmaf(da2, h[2], dx * bc1.x);  ap[2] *= da2;
            h[3] = fmaf(da3, h[3], dx * bc1.z);  ap[3] *= da3;
        }
        int si = chl * CH_STRIDE + sgm * 16 + s0;
        *(float4*)(s_hd + si) = make_float4(h[0], h[1], h[2], h[3]);
        *(float4*)(s_ap + si) = make_float4(ap[0], ap[1], ap[2], ap[3]);
    }
    __syncthreads();

    // ---- phase 2: serial propagation (warps 0..3; 16 lanes per channel) ----
    if (wid < 4) {
        int s  = lane & 15;
        int lp = wid * 2 + (lane >> 4);     // local pair 0..7
        float h = 0.f;
        for (int g = 0; g < NSEG; ++g) {
            int idx = lp * CH_STRIDE + g * 16 + s;
            float ap_ = s_ap[idx];
            float hd_ = s_hd[idx];
            s_ap[idx] = h;                  // segment-start state for phase3
            h = fmaf(ap_, h, hd_);
            float ss = h * h;
            ss += __shfl_xor_sync(0xffffffffu, ss, 8);
            ss += __shfl_xor_sync(0xffffffffu, ss, 4);
            ss += __shfl_xor_sync(0xffffffffu, ss, 2);
            ss += __shfl_xor_sync(0xffffffffu, ss, 1);
            if (ss > 100.0f) h *= 10.0f * rsqrtf(ss);
        }
    }
    __syncthreads();

    // ---- phase 3: re-run segments from true start states, emit gated y ----
    for (int sgm = wid * 4; sgm < wid * 4 + 4; ++sgm) {
        float4 hs = *(const float4*)(s_ap + chl * CH_STRIDE + sgm * 16 + s0);
        float h[4] = { hs.x, hs.y, hs.z, hs.w };
        int tb = sgm * SEGLEN;
        #pragma unroll
        for (int j = 0; j < SEGLEN; ++j) {
            int t = tb + j;
            float  d   = dl [(long)t * DINNER];
            float  xv  = __bfloat162float(xcb[(long)t * DINNER]);
            float4 bc0 = *(const float4*)(bcb + t * 32);
            float4 bc1 = *(const float4*)(bcb + t * 32 + 4);
            float  z   = zb [(long)t * 2 * DINNER];
            float dx = d * xv;
            float da0 = __expf(fmaxf(d * a[0], -10.f));
            float da1 = __expf(fmaxf(d * a[1], -10.f));
            float da2 = __expf(fmaxf(d * a[2], -10.f));
            float da3 = __expf(fmaxf(d * a[3], -10.f));
            h[0] = fmaf(da0, h[0], dx * bc0.x);
            h[1] = fmaf(da1, h[1], dx * bc0.z);
            h[2] = fmaf(da2, h[2], dx * bc1.x);
            h[3] = fmaf(da3, h[3], dx * bc1.z);
            if (j == SEGLEN - 1) {
                float ss = h[0]*h[0] + h[1]*h[1] + h[2]*h[2] + h[3]*h[3];
                ss += __shfl_xor_sync(0xffffffffu, ss, 1);
                ss += __shfl_xor_sync(0xffffffffu, ss, 2);
                if (ss > 100.0f) {
                    float r = 10.0f * rsqrtf(ss);
                    h[0] *= r; h[1] *= r; h[2] *= r; h[3] *= r;
                }
            }
            float p = h[0]*bc0.y + h[1]*bc0.w + h[2]*bc1.y + h[3]*bc1.w;
            p += __shfl_xor_sync(0xffffffffu, p, 1);
            p += __shfl_xor_sync(0xffffffffu, p, 2);
            if (sg == 0) {
                float yv = p + Dc * xv;
                yv *= z / (1.0f + __expf(-z));
                yb[(long)t * DINNER] = __float2bfloat16(yv);
            }
        }
    }
}

// ---------------------------------------------------------------------------
// Launch (7 kernels; capture slot index 3 = dt-GEMM)
// ---------------------------------------------------------------------------
extern "C" void kernel_launch(void* const* d_in, const int* in_sizes, int n_in,
                              void* d_out, int out_size) {
    const float* x             = (const float*)d_in[0];
    const float* in_proj_w     = (const float*)d_in[1];
    const float* in_proj_b     = (const float*)d_in[2];
    const float* conv_w        = (const float*)d_in[3];
    const float* conv_b        = (const float*)d_in[4];
    const float* x_proj_w      = (const float*)d_in[5];
    const float* x_proj_b      = (const float*)d_in[6];
    const float* dt_proj_w     = (const float*)d_in[7];
    const float* dt_proj_b     = (const float*)d_in[8];
    const float* A_log         = (const float*)d_in[9];
    const float* Dvec          = (const float*)d_in[10];
    const float* out_proj_w    = (const float*)d_in[11];
    const float* out_proj_b    = (const float*)d_in[12];
    const float* in_norm_alpha = (const float*)d_in[13];
    const float* in_norm_bias  = (const float*)d_in[14];
    const float* norm_alpha    = (const float*)d_in[15];
    const float* norm_bias     = (const float*)d_in[16];
    float* out = (float*)d_out;

    __nv_bfloat16 *xn_h, *wi_h, *wd_h, *wo_h, *xc_h, *y_h;
    float *xz, *delta, *obuf;
    cudaGetSymbolAddress((void**)&xn_h, g_xn_h);
    cudaGetSymbolAddress((void**)&wi_h, g_wi_h);
    cudaGetSymbolAddress((void**)&wd_h, g_wd_h);
    cudaGetSymbolAddress((void**)&wo_h, g_wo_h);
    cudaGetSymbolAddress((void**)&xc_h, g_xc_h);
    cudaGetSymbolAddress((void**)&y_h,  g_y_h);
    cudaGetSymbolAddress((void**)&xz,    g_xz);
    cudaGetSymbolAddress((void**)&delta, g_delta);
    cudaGetSymbolAddress((void**)&obuf,  g_out);

    cudaFuncSetAttribute(gemm_hmma<EPI_BIAS>,     cudaFuncAttributeMaxDynamicSharedMemorySize, GEMM_SMEM);
    cudaFuncSetAttribute(gemm_hmma<EPI_SOFTPLUS>, cudaFuncAttributeMaxDynamicSharedMemorySize, GEMM_SMEM);
    cudaFuncSetAttribute(gemm_hmma<EPI_RESID>,    cudaFuncAttributeMaxDynamicSharedMemorySize, GEMM_SMEM);
    cudaFuncSetAttribute(scan_fused,              cudaFuncAttributeMaxDynamicSharedMemorySize, SC_SMEM);

    // 0. fused: input LN + weight converts + g_bc bias seed
    ln_cvt_kernel<<<ROWS + CVT_BLOCKS + BC_BLOCKS, 256>>>(
        x, in_norm_alpha, in_norm_bias, xn_h,
        in_proj_w, dt_proj_w, out_proj_w, x_proj_b);
    // 1. in_proj (2048 x 4096 x 1024)
    gemm_hmma<EPI_BIAS><<<dim3(32, 16), 256, GEMM_SMEM>>>(
        xn_h, wi_h, in_proj_b, nullptr, xz, ROWS, 2 * DINNER, DMODEL);
    // 2. conv+silu fused into x_proj (K-parallel, atomic accumulate)
    xproj_conv_kernel<<<dim3(DINNER / XP_KCHUNK, ROWS / 32), 256>>>(
        x_proj_w, conv_w, conv_b);
    // 3. dt_proj + softplus + clip  <-- ncu capture slot
    gemm_hmma<EPI_SOFTPLUS><<<dim3(16, 16), 256, GEMM_SMEM>>>(
        xc_h, wd_h, dt_proj_b, nullptr, delta, ROWS, DINNER, DINNER);
    // 4. fused 3-phase selective scan + z gate
    scan_fused<<<512, 512, SC_SMEM>>>(A_log, Dvec);
    // 5. out_proj + residual (2048 x 1024 x 2048)
    gemm_hmma<EPI_RESID><<<dim3(8, 16), 256, GEMM_SMEM>>>(
        y_h, wo_h, out_proj_b, x, obuf, ROWS, DMODEL, DINNER);
    // 6. final layernorm -> d_out
    ln_out_kernel<<<ROWS, 256>>>(obuf, norm_alpha, norm_bias, out);
}

// round 16
// speedup vs baseline: 1.0300x; 1.0300x over previous
#include <cuda_runtime.h>
#include <cuda_bf16.h>
#include <cuda_fp8.h>
#include <math.h>
#include <stdint.h>

// ---------------------------------------------------------------------------
// Shapes (fixed): B=2, L=1024, d_model=1024, d_state=16, d_conv=4, d_inner=2048
// ---------------------------------------------------------------------------
#define BATCH    2
#define LSEQ     1024
#define DMODEL   1024
#define DSTATE   16
#define DCONV    4
#define DINNER   2048
#define ROWS     (BATCH * LSEQ)
#define NSEG     64
#define SEGLEN   16
#define WSCL     64.0f
#define WINV     (1.0f / 64.0f)

// ---------------------------------------------------------------------------
// Scratch (device globals; no allocation allowed). fp8 operands for GEMMs.
// ---------------------------------------------------------------------------
__device__ __nv_fp8_e4m3 g_xn_f8[ROWS * DMODEL];
__device__ __nv_fp8_e4m3 g_wi_f8[2 * DINNER * DMODEL];
__device__ __nv_fp8_e4m3 g_wd_f8[DINNER * DINNER];
__device__ __nv_fp8_e4m3 g_wo_f8[DMODEL * DINNER];
__device__ __nv_fp8_e4m3 g_xc_f8[ROWS * DINNER];
__device__ __nv_fp8_e4m3 g_y_f8 [ROWS * DINNER];
__device__ float g_xz   [ROWS * 2 * DINNER];
__device__ float g_bc   [ROWS * 2 * DSTATE];    // interleaved [t][s][{B,C}]
__device__ float g_delta[ROWS * DINNER];
__device__ float g_out  [ROWS * DMODEL];

// ---------------------------------------------------------------------------
// PTX helpers
// ---------------------------------------------------------------------------
__device__ __forceinline__ uint32_t smem_to_u32(const void* p) {
    uint32_t a;
    asm("{ .reg .u64 t; cvta.to.shared.u64 t, %1; cvt.u32.u64 %0, t; }" : "=r"(a) : "l"(p));
    return a;
}
#define CP_ASYNC16(dst, src) \
    asm volatile("cp.async.cg.shared.global [%0], [%1], 16;" :: "r"(dst), "l"(src))
#define CP_COMMIT() asm volatile("cp.async.commit_group;" ::: "memory")
#define CP_WAIT(n)  asm volatile("cp.async.wait_group %0;" :: "n"(n) : "memory")

__device__ __forceinline__ void ldsm_x4(uint32_t* r, uint32_t addr) {
    asm volatile("ldmatrix.sync.aligned.m8n8.x4.shared.b16 {%0,%1,%2,%3}, [%4];"
        : "=r"(r[0]), "=r"(r[1]), "=r"(r[2]), "=r"(r[3]) : "r"(addr));
}
// fp8 e4m3 MMA: m16n8k32, fp32 accumulate
__device__ __forceinline__ void mma_fp8(float* c, const uint32_t* a, const uint32_t* b) {
    asm volatile(
        "mma.sync.aligned.m16n8k32.row.col.f32.e4m3.e4m3.f32 "
        "{%0,%1,%2,%3}, {%4,%5,%6,%7}, {%8,%9}, {%0,%1,%2,%3};"
        : "+f"(c[0]), "+f"(c[1]), "+f"(c[2]), "+f"(c[3])
        : "r"(a[0]), "r"(a[1]), "r"(a[2]), "r"(a[3]), "r"(b[0]), "r"(b[1]));
}

__device__ __forceinline__ float warp_sum32(float v) {
    #pragma unroll
    for (int m = 16; m > 0; m >>= 1) v += __shfl_xor_sync(0xffffffffu, v, m);
    return v;
}
__device__ __forceinline__ uint32_t pack_fp8x4(float a, float b, float c, float d) {
    uint32_t lo = __nv_cvt_float2_to_fp8x2(make_float2(a, b), __NV_SATFINITE, __NV_E4M3);
    uint32_t hi = __nv_cvt_float2_to_fp8x2(make_float2(c, d), __NV_SATFINITE, __NV_E4M3);
    return (lo & 0xFFFFu) | (hi << 16);
}

// ---------------------------------------------------------------------------
// Fused: input LN (blocks 0..2047) + weight converts (x64 -> fp8) + bc seed
// ---------------------------------------------------------------------------
#define WI_N4 (2 * DINNER * DMODEL / 4)
#define WD_N4 (DINNER * DINNER / 4)
#define WO_N4 (DMODEL * DINNER / 4)
#define CVT_N4 (WI_N4 + WD_N4 + WO_N4)
#define CVT_BLOCKS ((CVT_N4 + 255) / 256)
#define BC_BLOCKS  (ROWS * 2 * DSTATE / 256)

__global__ void ln_cvt_kernel(const float* __restrict__ X,
                              const float* __restrict__ alpha,
                              const float* __restrict__ beta,
                              const float* __restrict__ Wi,
                              const float* __restrict__ Wd,
                              const float* __restrict__ Wo,
                              const float* __restrict__ xp_bias) {
    int tid = threadIdx.x;
    if (blockIdx.x >= ROWS + CVT_BLOCKS) {
        int i = (blockIdx.x - ROWS - CVT_BLOCKS) * 256 + tid;
        int p = i & 31;
        g_bc[i] = xp_bias[(p & 1) * 16 + (p >> 1)];
        return;
    }
    if (blockIdx.x >= ROWS) {
        long i = (long)(blockIdx.x - ROWS) * 256 + tid;
        if (i >= CVT_N4) return;
        const float* src; __nv_fp8_e4m3* dst; long idx;
        if (i < WI_N4)              { src = Wi; dst = g_wi_f8; idx = i; }
        else if (i < WI_N4 + WD_N4) { src = Wd; dst = g_wd_f8; idx = i - WI_N4; }
        else                        { src = Wo; dst = g_wo_f8; idx = i - WI_N4 - WD_N4; }
        float4 v = *(const float4*)(src + idx * 4);
        *(uint32_t*)(dst + idx * 4) =
            pack_fp8x4(v.x * WSCL, v.y * WSCL, v.z * WSCL, v.w * WSCL);
        return;
    }
    __shared__ float sh[2][8];
    int row = blockIdx.x;
    const float* xr = X + (long)row * DMODEL;
    float4 xv = *(const float4*)(xr + tid * 4);
    float s  = xv.x + xv.y + xv.z + xv.w;
    float ss = xv.x*xv.x + xv.y*xv.y + xv.z*xv.z + xv.w*xv.w;
    s = warp_sum32(s); ss = warp_sum32(ss);
    if ((tid & 31) == 0) { sh[0][tid >> 5] = s; sh[1][tid >> 5] = ss; }
    __syncthreads();
    float S = 0.f, SS = 0.f;
    #pragma unroll
    for (int w = 0; w < 8; ++w) { S += sh[0][w]; SS += sh[1][w]; }
    float mean = S * (1.0f / (float)DMODEL);
    float var  = fmaxf((SS - (float)DMODEL * mean * mean) * (1.0f / (float)(DMODEL - 1)), 0.f);
    float inv  = 1.0f / (sqrtf(var) + 1e-6f);
    float4 av = *(const float4*)(alpha + tid * 4);
    float4 bv = *(const float4*)(beta  + tid * 4);
    float o0 = av.x * (xv.x - mean) * inv + bv.x;
    float o1 = av.y * (xv.y - mean) * inv + bv.y;
    float o2 = av.z * (xv.z - mean) * inv + bv.z;
    float o3 = av.w * (xv.w - mean) * inv + bv.w;
    *(uint32_t*)(g_xn_f8 + (long)row * DMODEL + tid * 4) = pack_fp8x4(o0, o1, o2, o3);
}

// ---------------------------------------------------------------------------
// Final layernorm (fp32 out)
// ---------------------------------------------------------------------------
__global__ void ln_out_kernel(const float* __restrict__ X,
                              const float* __restrict__ alpha,
                              const float* __restrict__ beta,
                              float* __restrict__ Y) {
    __shared__ float sh[2][8];
    int row = blockIdx.x;
    int tid = threadIdx.x;
    const float* xr = X + (long)row * DMODEL;
    float4 xv = *(const float4*)(xr + tid * 4);
    float s  = xv.x + xv.y + xv.z + xv.w;
    float ss = xv.x*xv.x + xv.y*xv.y + xv.z*xv.z + xv.w*xv.w;
    s = warp_sum32(s); ss = warp_sum32(ss);
    if ((tid & 31) == 0) { sh[0][tid >> 5] = s; sh[1][tid >> 5] = ss; }
    __syncthreads();
    float S = 0.f, SS = 0.f;
    #pragma unroll
    for (int w = 0; w < 8; ++w) { S += sh[0][w]; SS += sh[1][w]; }
    float mean = S * (1.0f / (float)DMODEL);
    float var  = fmaxf((SS - (float)DMODEL * mean * mean) * (1.0f / (float)(DMODEL - 1)), 0.f);
    float inv  = 1.0f / (sqrtf(var) + 1e-6f);
    float4 av = *(const float4*)(alpha + tid * 4);
    float4 bv = *(const float4*)(beta  + tid * 4);
    float4 o;
    o.x = av.x * (xv.x - mean) * inv + bv.x;
    o.y = av.y * (xv.y - mean) * inv + bv.y;
    o.z = av.z * (xv.z - mean) * inv + bv.z;
    o.w = av.w * (xv.w - mean) * inv + bv.w;
    *(float4*)(Y + (long)row * DMODEL + tid * 4) = o;
}

// ---------------------------------------------------------------------------
// GEMM epilogues (acc arrives scaled by WSCL; multiply by WINV first)
// ---------------------------------------------------------------------------
#define EPI_BIAS     0
#define EPI_SOFTPLUS 1
#define EPI_RESID    2
__device__ __forceinline__ float epi_apply(int EPI, float t, float r) {
    if (EPI == EPI_SOFTPLUS) {
        float sp = fmaxf(t, 0.f) + log1pf(expf(-fabsf(t)));
        t = fminf(fmaxf(sp, 1e-4f), 10.0f);
    } else if (EPI == EPI_RESID) {
        t += r;
    }
    return t;
}

// ---------------------------------------------------------------------------
// gemm_fp8: block 128x128, 8 warps, warp tile 64x32, 64 fp8 K per kt,
// 4-stage cp.async, 2 CTA/SM. Same smem/ldmatrix geometry as the bf16 kernel
// (bytes identical); mma is m16n8k32 e4m3.
// ---------------------------------------------------------------------------
#define ROWB      80
#define ARR_SZ    (128 * ROWB)
#define STAGE_SZ  (2 * ARR_SZ)
#define NSTAGE    4
#define GEMM_SMEM (NSTAGE * STAGE_SZ)

template<int EPI>
__global__ __launch_bounds__(256, 2)
void gemm_fp8(const __nv_fp8_e4m3* __restrict__ A, const __nv_fp8_e4m3* __restrict__ B,
              const float* __restrict__ bias, const float* __restrict__ resid,
              float* __restrict__ C, int M, int N, int K) {
    extern __shared__ char smem[];
    uint32_t sb = smem_to_u32(smem);
    int tid  = threadIdx.x;
    int lane = tid & 31;
    int wid  = tid >> 5;
    int wm   = wid & 1;
    int wn   = wid >> 1;
    int bm = blockIdx.y * 128, bn = blockIdx.x * 128;

    const __nv_fp8_e4m3* srcs[2] = { A + (long)bm * K, B + (long)bn * K };

    int s_arr[4], s_row[4], s_c[4];
    #pragma unroll
    for (int i = 0; i < 4; ++i) {
        int id = tid + i * 256;
        s_arr[i] = id >> 9;
        int rem = id & 511;
        s_row[i] = rem >> 2;
        s_c[i]   = rem & 3;
    }

    auto load_stage = [&](int kt, int buf) {
        #pragma unroll
        for (int i = 0; i < 4; ++i) {
            uint32_t dst = sb + buf * STAGE_SZ + s_arr[i] * ARR_SZ
                         + s_row[i] * ROWB + s_c[i] * 16;
            const __nv_fp8_e4m3* src = srcs[s_arr[i]] + (long)s_row[i] * K
                                     + kt * 64 + s_c[i] * 16;
            CP_ASYNC16(dst, src);
        }
        CP_COMMIT();
    };

    float c[4][4][4];
    #pragma unroll
    for (int mt = 0; mt < 4; ++mt)
        #pragma unroll
        for (int nj = 0; nj < 4; ++nj)
            #pragma unroll
            for (int r = 0; r < 4; ++r) c[mt][nj][r] = 0.f;

    int a_row = wm * 64 + (lane & 15);
    int a_kb  = (lane >> 4) << 4;
    int b_row = wn * 32 + ((lane >> 4) << 3) + (lane & 7);
    int b_kb  = ((lane >> 3) & 1) << 4;

    auto load_frags = [&](uint32_t base, int ks, uint32_t a[4][4], uint32_t b[4][2]) {
        uint32_t kboff = ks * 32;
        #pragma unroll
        for (int mt = 0; mt < 4; ++mt) {
            uint32_t off = (uint32_t)((a_row + mt * 16) * ROWB) + a_kb + kboff;
            ldsm_x4(a[mt], base + off);
        }
        #pragma unroll
        for (int nt = 0; nt < 2; ++nt) {
            uint32_t off = (uint32_t)((b_row + nt * 16) * ROWB) + b_kb + kboff;
            uint32_t t0[4];
            ldsm_x4(t0, base + ARR_SZ + off);
            b[nt*2][0]   = t0[0]; b[nt*2][1]   = t0[1];
            b[nt*2+1][0] = t0[2]; b[nt*2+1][1] = t0[3];
        }
    };
    auto do_mmas = [&](uint32_t a[4][4], uint32_t b[4][2]) {
        #pragma unroll
        for (int mt = 0; mt < 4; ++mt)
            #pragma unroll
            for (int nj = 0; nj < 4; ++nj)
                mma_fp8(c[mt][nj], a[mt], b[nj]);
    };

    const int KT = K >> 6;                    // 64 fp8 per kt
    load_stage(0, 0);
    load_stage(1, 1);
    load_stage(2, 2);
    int buf = 0;
    for (int kt = 0; kt < KT; ++kt) {
        if (kt + 3 < KT) {
            int nb = buf + 3; if (nb >= NSTAGE) nb -= NSTAGE;
            load_stage(kt + 3, nb);
            CP_WAIT(3);
        } else if (kt + 2 < KT) { CP_WAIT(2); }
        else if (kt + 1 < KT)   { CP_WAIT(1); }
        else                    { CP_WAIT(0); }
        __syncthreads();

        uint32_t base = sb + buf * STAGE_SZ;
        uint32_t a0[4][4], b0[4][2], a1[4][4], b1[4][2];
        load_frags(base, 0, a0, b0);          // k bytes 0-31  (k32)
        load_frags(base, 1, a1, b1);          // k bytes 32-63 (k32)
        do_mmas(a0, b0);
        do_mmas(a1, b1);
        __syncthreads();
        if (++buf == NSTAGE) buf = 0;
    }

    #pragma unroll
    for (int mt = 0; mt < 4; ++mt) {
        #pragma unroll
        for (int nj = 0; nj < 4; ++nj) {
            int row0 = bm + wm * 64 + mt * 16 + (lane >> 2);
            int col  = bn + wn * 32 + nj * 8 + (lane & 3) * 2;
            float b0 = bias[col], b1 = bias[col + 1];
            long p0 = (long)row0 * N + col, p1 = (long)(row0 + 8) * N + col;
            float r0 = (EPI == EPI_RESID) ? resid[p0]     : 0.f;
            float r1 = (EPI == EPI_RESID) ? resid[p0 + 1] : 0.f;
            float r2 = (EPI == EPI_RESID) ? resid[p1]     : 0.f;
            float r3 = (EPI == EPI_RESID) ? resid[p1 + 1] : 0.f;
            float v0 = epi_apply(EPI, c[mt][nj][0] * WINV + b0, r0);
            float v1 = epi_apply(EPI, c[mt][nj][1] * WINV + b1, r1);
            float v2 = epi_apply(EPI, c[mt][nj][2] * WINV + b0, r2);
            float v3 = epi_apply(EPI, c[mt][nj][3] * WINV + b1, r3);
            *(float2*)(C + p0) = make_float2(v0, v1);
            *(float2*)(C + p1) = make_float2(v2, v3);
        }
    }
}

// ---------------------------------------------------------------------------
// x_proj fused with causal conv(4)+SiLU. Grid (8 kchunks, 64 rowtiles).
// Conv from g_xz (fp32), BC accumulated in fp32, xc emitted as fp8.
// ---------------------------------------------------------------------------
#define XP_KCHUNK 256
__global__ __launch_bounds__(256)
void xproj_conv_kernel(const float* __restrict__ W,
                       const float* __restrict__ conv_w,
                       const float* __restrict__ conv_b) {
    __shared__ float Xs[32][65];
    __shared__ float Ws[32][65];
    __shared__ float Cw[XP_KCHUNK][4];
    __shared__ float Cb[XP_KCHUNK];
    int tid = threadIdx.x;
    int kbase = blockIdx.x * XP_KCHUNK;
    int row0  = blockIdx.y * 32;
    if (tid < XP_KCHUNK) {
        float4 w = *(const float4*)(conv_w + (long)(kbase + tid) * 4);
        Cw[tid][0] = w.x; Cw[tid][1] = w.y; Cw[tid][2] = w.z; Cw[tid][3] = w.w;
        Cb[tid] = conv_b[kbase + tid];
    }
    __syncthreads();

    int rg = (tid >> 5) * 4;
    int n  = tid & 31;
    float acc[4] = {0.f, 0.f, 0.f, 0.f};
    for (int k0 = kbase; k0 < kbase + XP_KCHUNK; k0 += 64) {
        #pragma unroll
        for (int i = 0; i < 2; ++i) {
            int id = tid * 2 + i;
            int r = id >> 4, c4 = (id & 15) * 4;
            int row = row0 + r;
            int t = row & (LSEQ - 1);
            const float* xp = g_xz + (long)row * (2 * DINNER) + k0 + c4;
            float4 zf = make_float4(0.f, 0.f, 0.f, 0.f);
            float4 v3 = *(const float4*)xp;
            float4 v2 = (t >= 1) ? *(const float4*)(xp - 1 * 2 * DINNER) : zf;
            float4 v1 = (t >= 2) ? *(const float4*)(xp - 2 * 2 * DINNER) : zf;
            float4 v0 = (t >= 3) ? *(const float4*)(xp - 3 * 2 * DINNER) : zf;
            int ci = k0 + c4 - kbase;
            float o[4];
            o[0] = Cb[ci+0] + v0.x*Cw[ci+0][0] + v1.x*Cw[ci+0][1] + v2.x*Cw[ci+0][2] + v3.x*Cw[ci+0][3];
            o[1] = Cb[ci+1] + v0.y*Cw[ci+1][0] + v1.y*Cw[ci+1][1] + v2.y*Cw[ci+1][2] + v3.y*Cw[ci+1][3];
            o[2] = Cb[ci+2] + v0.z*Cw[ci+2][0] + v1.z*Cw[ci+2][1] + v2.z*Cw[ci+2][2] + v3.z*Cw[ci+2][3];
            o[3] = Cb[ci+3] + v0.w*Cw[ci+3][0] + v1.w*Cw[ci+3][1] + v2.w*Cw[ci+3][2] + v3.w*Cw[ci+3][3];
            #pragma unroll
            for (int k = 0; k < 4; ++k) {
                o[k] = o[k] / (1.0f + expf(-o[k]));     // silu
                Xs[r][c4 + k] = o[k];
            }
            *(uint32_t*)(g_xc_f8 + (long)row * DINNER + k0 + c4) =
                pack_fp8x4(o[0], o[1], o[2], o[3]);
            float4 wv = *(const float4*)(W + (long)r * DINNER + k0 + c4);
            Ws[r][c4] = wv.x; Ws[r][c4+1] = wv.y; Ws[r][c4+2] = wv.z; Ws[r][c4+3] = wv.w;
        }
        __syncthreads();
        #pragma unroll
        for (int kk = 0; kk < 64; ++kk) {
            float w = Ws[n][kk];
            #pragma unroll
            for (int i = 0; i < 4; ++i) acc[i] = fmaf(Xs[rg + i][kk], w, acc[i]);
        }
        __syncthreads();
    }
    int off = (n & 15) * 2 + (n >> 4);
    #pragma unroll
    for (int i = 0; i < 4; ++i)
        atomicAdd(&g_bc[(long)(row0 + rg + i) * 32 + off], acc[i]);
}

// ---------------------------------------------------------------------------
// Fused chunked selective scan (3 phases in one kernel); xc fp8, y fp8.
// ---------------------------------------------------------------------------
#define CH_STRIDE 1032
#define SC_SMEM  (2 * 8 * CH_STRIDE * 4)

__global__ __launch_bounds__(512, 2)
void scan_fused(const float* __restrict__ A_log, const float* __restrict__ Dvec) {
    extern __shared__ float sm[];
    float* s_ap = sm;
    float* s_hd = sm + 8 * CH_STRIDE;

    int tid  = threadIdx.x;
    int wid  = tid >> 5;
    int lane = tid & 31;
    int chl  = lane >> 2;
    int sg   = lane & 3;
    int s0   = sg * 4;
    int pair = blockIdx.x * 8 + chl;
    int b = pair >> 11;
    int c = pair & (DINNER - 1);

    float a[4];
    #pragma unroll
    for (int k = 0; k < 4; ++k) a[k] = -expf(A_log[c * DSTATE + s0 + k]);
    float Dc = Dvec[c];

    const float* dl  = g_delta + (long)b * LSEQ * DINNER + c;
    const __nv_fp8_e4m3* xcb = g_xc_f8 + (long)b * LSEQ * DINNER + c;
    const float* bcb = g_bc + (long)b * LSEQ * 32 + s0 * 2;
    const float* zb  = g_xz + (long)b * LSEQ * 2 * DINNER + DINNER + c;
    __nv_fp8_e4m3* yb = g_y_f8 + (long)b * LSEQ * DINNER + c;

    // phase 1
    for (int sgm = wid * 4; sgm < wid * 4 + 4; ++sgm) {
        float h[4] = {0.f, 0.f, 0.f, 0.f};
        float ap[4] = {1.f, 1.f, 1.f, 1.f};
        int tb = sgm * SEGLEN;
        #pragma unroll
        for (int j = 0; j < SEGLEN; ++j) {
            int t = tb + j;
            float  d   = dl [(long)t * DINNER];
            float  xv  = float(xcb[(long)t * DINNER]);
            float4 bc0 = *(const float4*)(bcb + t * 32);
            float4 bc1 = *(const float4*)(bcb + t * 32 + 4);
            float dx = d * xv;
            float da0 = __expf(fmaxf(d * a[0], -10.f));
            float da1 = __expf(fmaxf(d * a[1], -10.f));
            float da2 = __expf(fmaxf(d * a[2], -10.f));
            float da3 = __expf(fmaxf(d * a[3], -10.f));
            h[0] = fmaf(da0, h[0], dx * bc0.x);  ap[0] *= da0;
            h[1] = fmaf(da1, h[1], dx * bc0.z);  ap[1] *= da1;
            h[2] = fmaf(da2, h[2], dx * bc1.x);  ap[2] *= da2;
            h[3] = fmaf(da3, h[3], dx * bc1.z);  ap[3] *= da3;
        }
        int si = chl * CH_STRIDE + sgm * 16 + s0;
        *(float4*)(s_hd + si) = make_float4(h[0], h[1], h[2], h[3]);
        *(float4*)(s_ap + si) = make_float4(ap[0], ap[1], ap[2], ap[3]);
    }
    __syncthreads();

    // phase 2
    if (wid < 4) {
        int s  = lane & 15;
        int lp = wid * 2 + (lane >> 4);
        float h = 0.f;
        for (int g = 0; g < NSEG; ++g) {
            int idx = lp * CH_STRIDE + g * 16 + s;
            float ap_ = s_ap[idx];
            float hd_ = s_hd[idx];
            s_ap[idx] = h;
            h = fmaf(ap_, h, hd_);
            float ss = h * h;
            ss += __shfl_xor_sync(0xffffffffu, ss, 8);
            ss += __shfl_xor_sync(0xffffffffu, ss, 4);
            ss += __shfl_xor_sync(0xffffffffu, ss, 2);
            ss += __shfl_xor_sync(0xffffffffu, ss, 1);
            if (ss > 100.0f) h *= 10.0f * rsqrtf(ss);
        }
    }
    __syncthreads();

    // phase 3
    for (int sgm = wid * 4; sgm < wid * 4 + 4; ++sgm) {
        float4 hs = *(const float4*)(s_ap + chl * CH_STRIDE + sgm * 16 + s0);
        float h[4] = { hs.x, hs.y, hs.z, hs.w };
        int tb = sgm * SEGLEN;
        #pragma unroll
        for (int j = 0; j < SEGLEN; ++j) {
            int t = tb + j;
            float  d   = dl [(long)t * DINNER];
            float  xv  = float(xcb[(long)t * DINNER]);
            float4 bc0 = *(const float4*)(bcb + t * 32);
            float4 bc1 = *(const float4*)(bcb + t * 32 + 4);
            float  z   = zb [(long)t * 2 * DINNER];
            float dx = d * xv;
            float da0 = __expf(fmaxf(d * a[0], -10.f));
            float da1 = __expf(fmaxf(d * a[1], -10.f));
            float da2 = __expf(fmaxf(d * a[2], -10.f));
            float da3 = __expf(fmaxf(d * a[3], -10.f));
            h[0] = fmaf(da0, h[0], dx * bc0.x);
            h[1] = fmaf(da1, h[1], dx * bc0.z);
            h[2] = fmaf(da2, h[2], dx * bc1.x);
            h[3] = fmaf(da3, h[3], dx * bc1.z);
            if (j == SEGLEN - 1) {
                float ss = h[0]*h[0] + h[1]*h[1] + h[2]*h[2] + h[3]*h[3];
                ss += __shfl_xor_sync(0xffffffffu, ss, 1);
                ss += __shfl_xor_sync(0xffffffffu, ss, 2);
                if (ss > 100.0f) {
                    float r = 10.0f * rsqrtf(ss);
                    h[0] *= r; h[1] *= r; h[2] *= r; h[3] *= r;
                }
            }
            float p = h[0]*bc0.y + h[1]*bc0.w + h[2]*bc1.y + h[3]*bc1.w;
            p += __shfl_xor_sync(0xffffffffu, p, 1);
            p += __shfl_xor_sync(0xffffffffu, p, 2);
            if (sg == 0) {
                float yv = p + Dc * xv;
                yv *= z / (1.0f + __expf(-z));
                yb[(long)t * DINNER] = __nv_fp8_e4m3(yv);
            }
        }
    }
}

// ---------------------------------------------------------------------------
// Launch (7 kernels; capture slot index 3 = dt-GEMM fp8)
// ---------------------------------------------------------------------------
extern "C" void kernel_launch(void* const* d_in, const int* in_sizes, int n_in,
                              void* d_out, int out_size) {
    const float* x             = (const float*)d_in[0];
    const float* in_proj_w     = (const float*)d_in[1];
    const float* in_proj_b     = (const float*)d_in[2];
    const float* conv_w        = (const float*)d_in[3];
    const float* conv_b        = (const float*)d_in[4];
    const float* x_proj_w      = (const float*)d_in[5];
    const float* x_proj_b      = (const float*)d_in[6];
    const float* dt_proj_w     = (const float*)d_in[7];
    const float* dt_proj_b     = (const float*)d_in[8];
    const float* A_log         = (const float*)d_in[9];
    const float* Dvec          = (const float*)d_in[10];
    const float* out_proj_w    = (const float*)d_in[11];
    const float* out_proj_b    = (const float*)d_in[12];
    const float* in_norm_alpha = (const float*)d_in[13];
    const float* in_norm_bias  = (const float*)d_in[14];
    const float* norm_alpha    = (const float*)d_in[15];
    const float* norm_bias     = (const float*)d_in[16];
    float* out = (float*)d_out;

    __nv_fp8_e4m3 *xn_f, *wi_f, *wd_f, *wo_f, *xc_f, *y_f;
    float *xz, *delta, *obuf;
    cudaGetSymbolAddress((void**)&xn_f, g_xn_f8);
    cudaGetSymbolAddress((void**)&wi_f, g_wi_f8);
    cudaGetSymbolAddress((void**)&wd_f, g_wd_f8);
    cudaGetSymbolAddress((void**)&wo_f, g_wo_f8);
    cudaGetSymbolAddress((void**)&xc_f, g_xc_f8);
    cudaGetSymbolAddress((void**)&y_f,  g_y_f8);
    cudaGetSymbolAddress((void**)&xz,    g_xz);
    cudaGetSymbolAddress((void**)&delta, g_delta);
    cudaGetSymbolAddress((void**)&obuf,  g_out);

    cudaFuncSetAttribute(gemm_fp8<EPI_BIAS>,     cudaFuncAttributeMaxDynamicSharedMemorySize, GEMM_SMEM);
    cudaFuncSetAttribute(gemm_fp8<EPI_SOFTPLUS>, cudaFuncAttributeMaxDynamicSharedMemorySize, GEMM_SMEM);
    cudaFuncSetAttribute(gemm_fp8<EPI_RESID>,    cudaFuncAttributeMaxDynamicSharedMemorySize, GEMM_SMEM);
    cudaFuncSetAttribute(scan_fused,             cudaFuncAttributeMaxDynamicSharedMemorySize, SC_SMEM);

    // 0. fused: input LN (fp8 out) + weight converts (x64 -> fp8) + bc seed
    ln_cvt_kernel<<<ROWS + CVT_BLOCKS + BC_BLOCKS, 256>>>(
        x, in_norm_alpha, in_norm_bias,
        in_proj_w, dt_proj_w, out_proj_w, x_proj_b);
    // 1. in_proj (2048 x 4096 x 1024) fp8
    gemm_fp8<EPI_BIAS><<<dim3(32, 16), 256, GEMM_SMEM>>>(
        xn_f, wi_f, in_proj_b, nullptr, xz, ROWS, 2 * DINNER, DMODEL);
    // 2. conv+silu fused into x_proj (K-parallel, atomic accumulate)
    xproj_conv_kernel<<<dim3(DINNER / XP_KCHUNK, ROWS / 32), 256>>>(
        x_proj_w, conv_w, conv_b);
    // 3. dt_proj + softplus + clip fp8  <-- ncu capture slot
    gemm_fp8<EPI_SOFTPLUS><<<dim3(16, 16), 256, GEMM_SMEM>>>(
        xc_f, wd_f, dt_proj_b, nullptr, delta, ROWS, DINNER, DINNER);
    // 4. fused 3-phase selective scan + z gate
    scan_fused<<<512, 512, SC_SMEM>>>(A_log, Dvec);
    // 5. out_proj + residual (2048 x 1024 x 2048) fp8
    gemm_fp8<EPI_RESID><<<dim3(8, 16), 256, GEMM_SMEM>>>(
        y_f, wo_f, out_proj_b, x, obuf, ROWS, DMODEL, DINNER);
    // 6. final layernorm -> d_out
    ln_out_kernel<<<ROWS, 256>>>(obuf, norm_alpha, norm_bias, out);
}

// round 17
// speedup vs baseline: 1.0543x; 1.0236x over previous
#include <cuda_runtime.h>
#include <cuda_bf16.h>
#include <cuda_fp8.h>
#include <math.h>
#include <stdint.h>

// ---------------------------------------------------------------------------
// Shapes (fixed): B=2, L=1024, d_model=1024, d_state=16, d_conv=4, d_inner=2048
// ---------------------------------------------------------------------------
#define BATCH    2
#define LSEQ     1024
#define DMODEL   1024
#define DSTATE   16
#define DCONV    4
#define DINNER   2048
#define ROWS     (BATCH * LSEQ)
#define NSEG     64
#define SEGLEN   16
#define WSCL     64.0f
#define WINV     (1.0f / 64.0f)

// ---------------------------------------------------------------------------
// Scratch (device globals; no allocation allowed). fp8 operands for GEMMs.
// ---------------------------------------------------------------------------
__device__ __nv_fp8_e4m3 g_xn_f8[ROWS * DMODEL];
__device__ __nv_fp8_e4m3 g_wi_f8[2 * DINNER * DMODEL];
__device__ __nv_fp8_e4m3 g_wd_f8[DINNER * DINNER];
__device__ __nv_fp8_e4m3 g_wo_f8[DMODEL * DINNER];
__device__ __nv_fp8_e4m3 g_xc_f8[ROWS * DINNER];
__device__ __nv_fp8_e4m3 g_y_f8 [ROWS * DINNER];
__device__ float g_xz   [ROWS * 2 * DINNER];
__device__ float g_bc   [ROWS * 2 * DSTATE];    // interleaved [t][s][{B,C}]
__device__ float g_delta[ROWS * DINNER];
__device__ float g_out  [ROWS * DMODEL];

// ---------------------------------------------------------------------------
// PTX helpers
// ---------------------------------------------------------------------------
__device__ __forceinline__ uint32_t smem_to_u32(const void* p) {
    uint32_t a;
    asm("{ .reg .u64 t; cvta.to.shared.u64 t, %1; cvt.u32.u64 %0, t; }" : "=r"(a) : "l"(p));
    return a;
}
#define CP_ASYNC16(dst, src) \
    asm volatile("cp.async.cg.shared.global [%0], [%1], 16;" :: "r"(dst), "l"(src))
#define CP_COMMIT() asm volatile("cp.async.commit_group;" ::: "memory")
#define CP_WAIT(n)  asm volatile("cp.async.wait_group %0;" :: "n"(n) : "memory")

__device__ __forceinline__ void ldsm_x4(uint32_t* r, uint32_t addr) {
    asm volatile("ldmatrix.sync.aligned.m8n8.x4.shared.b16 {%0,%1,%2,%3}, [%4];"
        : "=r"(r[0]), "=r"(r[1]), "=r"(r[2]), "=r"(r[3]) : "r"(addr));
}
__device__ __forceinline__ void mma_fp8(float* c, const uint32_t* a, const uint32_t* b) {
    asm volatile(
        "mma.sync.aligned.m16n8k32.row.col.f32.e4m3.e4m3.f32 "
        "{%0,%1,%2,%3}, {%4,%5,%6,%7}, {%8,%9}, {%0,%1,%2,%3};"
        : "+f"(c[0]), "+f"(c[1]), "+f"(c[2]), "+f"(c[3])
        : "r"(a[0]), "r"(a[1]), "r"(a[2]), "r"(a[3]), "r"(b[0]), "r"(b[1]));
}

__device__ __forceinline__ float warp_sum32(float v) {
    #pragma unroll
    for (int m = 16; m > 0; m >>= 1) v += __shfl_xor_sync(0xffffffffu, v, m);
    return v;
}
__device__ __forceinline__ uint32_t pack_fp8x4(float a, float b, float c, float d) {
    uint32_t lo = __nv_cvt_float2_to_fp8x2(make_float2(a, b), __NV_SATFINITE, __NV_E4M3);
    uint32_t hi = __nv_cvt_float2_to_fp8x2(make_float2(c, d), __NV_SATFINITE, __NV_E4M3);
    return (lo & 0xFFFFu) | (hi << 16);
}

// ---------------------------------------------------------------------------
// Fused: input LN + weight converts (x64 -> fp8) + bc seed
// ---------------------------------------------------------------------------
#define WI_N4 (2 * DINNER * DMODEL / 4)
#define WD_N4 (DINNER * DINNER / 4)
#define WO_N4 (DMODEL * DINNER / 4)
#define CVT_N4 (WI_N4 + WD_N4 + WO_N4)
#define CVT_BLOCKS ((CVT_N4 + 255) / 256)
#define BC_BLOCKS  (ROWS * 2 * DSTATE / 256)

__global__ void ln_cvt_kernel(const float* __restrict__ X,
                              const float* __restrict__ alpha,
                              const float* __restrict__ beta,
                              const float* __restrict__ Wi,
                              const float* __restrict__ Wd,
                              const float* __restrict__ Wo,
                              const float* __restrict__ xp_bias) {
    int tid = threadIdx.x;
    if (blockIdx.x >= ROWS + CVT_BLOCKS) {
        int i = (blockIdx.x - ROWS - CVT_BLOCKS) * 256 + tid;
        int p = i & 31;
        g_bc[i] = xp_bias[(p & 1) * 16 + (p >> 1)];
        return;
    }
    if (blockIdx.x >= ROWS) {
        long i = (long)(blockIdx.x - ROWS) * 256 + tid;
        if (i >= CVT_N4) return;
        const float* src; __nv_fp8_e4m3* dst; long idx;
        if (i < WI_N4)              { src = Wi; dst = g_wi_f8; idx = i; }
        else if (i < WI_N4 + WD_N4) { src = Wd; dst = g_wd_f8; idx = i - WI_N4; }
        else                        { src = Wo; dst = g_wo_f8; idx = i - WI_N4 - WD_N4; }
        float4 v = *(const float4*)(src + idx * 4);
        *(uint32_t*)(dst + idx * 4) =
            pack_fp8x4(v.x * WSCL, v.y * WSCL, v.z * WSCL, v.w * WSCL);
        return;
    }
    __shared__ float sh[2][8];
    int row = blockIdx.x;
    const float* xr = X + (long)row * DMODEL;
    float4 xv = *(const float4*)(xr + tid * 4);
    float s  = xv.x + xv.y + xv.z + xv.w;
    float ss = xv.x*xv.x + xv.y*xv.y + xv.z*xv.z + xv.w*xv.w;
    s = warp_sum32(s); ss = warp_sum32(ss);
    if ((tid & 31) == 0) { sh[0][tid >> 5] = s; sh[1][tid >> 5] = ss; }
    __syncthreads();
    float S = 0.f, SS = 0.f;
    #pragma unroll
    for (int w = 0; w < 8; ++w) { S += sh[0][w]; SS += sh[1][w]; }
    float mean = S * (1.0f / (float)DMODEL);
    float var  = fmaxf((SS - (float)DMODEL * mean * mean) * (1.0f / (float)(DMODEL - 1)), 0.f);
    float inv  = 1.0f / (sqrtf(var) + 1e-6f);
    float4 av = *(const float4*)(alpha + tid * 4);
    float4 bv = *(const float4*)(beta  + tid * 4);
    float o0 = av.x * (xv.x - mean) * inv + bv.x;
    float o1 = av.y * (xv.y - mean) * inv + bv.y;
    float o2 = av.z * (xv.z - mean) * inv + bv.z;
    float o3 = av.w * (xv.w - mean) * inv + bv.w;
    *(uint32_t*)(g_xn_f8 + (long)row * DMODEL + tid * 4) = pack_fp8x4(o0, o1, o2, o3);
}

// ---------------------------------------------------------------------------
// Final layernorm (fp32 out)
// ---------------------------------------------------------------------------
__global__ void ln_out_kernel(const float* __restrict__ X,
                              const float* __restrict__ alpha,
                              const float* __restrict__ beta,
                              float* __restrict__ Y) {
    __shared__ float sh[2][8];
    int row = blockIdx.x;
    int tid = threadIdx.x;
    const float* xr = X + (long)row * DMODEL;
    float4 xv = *(const float4*)(xr + tid * 4);
    float s  = xv.x + xv.y + xv.z + xv.w;
    float ss = xv.x*xv.x + xv.y*xv.y + xv.z*xv.z + xv.w*xv.w;
    s = warp_sum32(s); ss = warp_sum32(ss);
    if ((tid & 31) == 0) { sh[0][tid >> 5] = s; sh[1][tid >> 5] = ss; }
    __syncthreads();
    float S = 0.f, SS = 0.f;
    #pragma unroll
    for (int w = 0; w < 8; ++w) { S += sh[0][w]; SS += sh[1][w]; }
    float mean = S * (1.0f / (float)DMODEL);
    float var  = fmaxf((SS - (float)DMODEL * mean * mean) * (1.0f / (float)(DMODEL - 1)), 0.f);
    float inv  = 1.0f / (sqrtf(var) + 1e-6f);
    float4 av = *(const float4*)(alpha + tid * 4);
    float4 bv = *(const float4*)(beta  + tid * 4);
    float4 o;
    o.x = av.x * (xv.x - mean) * inv + bv.x;
    o.y = av.y * (xv.y - mean) * inv + bv.y;
    o.z = av.z * (xv.z - mean) * inv + bv.z;
    o.w = av.w * (xv.w - mean) * inv + bv.w;
    *(float4*)(Y + (long)row * DMODEL + tid * 4) = o;
}

// ---------------------------------------------------------------------------
// GEMM epilogues (acc arrives scaled by WSCL; multiply by WINV first)
// ---------------------------------------------------------------------------
#define EPI_BIAS     0
#define EPI_SOFTPLUS 1
#define EPI_RESID    2
__device__ __forceinline__ float epi_apply(int EPI, float t, float r) {
    if (EPI == EPI_SOFTPLUS) {
        float sp = fmaxf(t, 0.f) + log1pf(expf(-fabsf(t)));
        t = fminf(fmaxf(sp, 1e-4f), 10.0f);
    } else if (EPI == EPI_RESID) {
        t += r;
    }
    return t;
}

// ---------------------------------------------------------------------------
// gemm_fp8: block 128x128, warp tile 64x32, 64 fp8 K/kt, 4-stage, 2 CTA/SM
// ---------------------------------------------------------------------------
#define ROWB      80
#define ARR_SZ    (128 * ROWB)
#define STAGE_SZ  (2 * ARR_SZ)
#define NSTAGE    4
#define GEMM_SMEM (NSTAGE * STAGE_SZ)

template<int EPI>
__global__ __launch_bounds__(256, 2)
void gemm_fp8(const __nv_fp8_e4m3* __restrict__ A, const __nv_fp8_e4m3* __restrict__ B,
              const float* __restrict__ bias, const float* __restrict__ resid,
              float* __restrict__ C, int M, int N, int K) {
    extern __shared__ char smem[];
    uint32_t sb = smem_to_u32(smem);
    int tid  = threadIdx.x;
    int lane = tid & 31;
    int wid  = tid >> 5;
    int wm   = wid & 1;
    int wn   = wid >> 1;
    int bm = blockIdx.y * 128, bn = blockIdx.x * 128;

    const __nv_fp8_e4m3* srcs[2] = { A + (long)bm * K, B + (long)bn * K };

    int s_arr[4], s_row[4], s_c[4];
    #pragma unroll
    for (int i = 0; i < 4; ++i) {
        int id = tid + i * 256;
        s_arr[i] = id >> 9;
        int rem = id & 511;
        s_row[i] = rem >> 2;
        s_c[i]   = rem & 3;
    }

    auto load_stage = [&](int kt, int buf) {
        #pragma unroll
        for (int i = 0; i < 4; ++i) {
            uint32_t dst = sb + buf * STAGE_SZ + s_arr[i] * ARR_SZ
                         + s_row[i] * ROWB + s_c[i] * 16;
            const __nv_fp8_e4m3* src = srcs[s_arr[i]] + (long)s_row[i] * K
                                     + kt * 64 + s_c[i] * 16;
            CP_ASYNC16(dst, src);
        }
        CP_COMMIT();
    };

    float c[4][4][4];
    #pragma unroll
    for (int mt = 0; mt < 4; ++mt)
        #pragma unroll
        for (int nj = 0; nj < 4; ++nj)
            #pragma unroll
            for (int r = 0; r < 4; ++r) c[mt][nj][r] = 0.f;

    int a_row = wm * 64 + (lane & 15);
    int a_kb  = (lane >> 4) << 4;
    int b_row = wn * 32 + ((lane >> 4) << 3) + (lane & 7);
    int b_kb  = ((lane >> 3) & 1) << 4;

    auto load_frags = [&](uint32_t base, int ks, uint32_t a[4][4], uint32_t b[4][2]) {
        uint32_t kboff = ks * 32;
        #pragma unroll
        for (int mt = 0; mt < 4; ++mt) {
            uint32_t off = (uint32_t)((a_row + mt * 16) * ROWB) + a_kb + kboff;
            ldsm_x4(a[mt], base + off);
        }
        #pragma unroll
        for (int nt = 0; nt < 2; ++nt) {
            uint32_t off = (uint32_t)((b_row + nt * 16) * ROWB) + b_kb + kboff;
            uint32_t t0[4];
            ldsm_x4(t0, base + ARR_SZ + off);
            b[nt*2][0]   = t0[0]; b[nt*2][1]   = t0[1];
            b[nt*2+1][0] = t0[2]; b[nt*2+1][1] = t0[3];
        }
    };
    auto do_mmas = [&](uint32_t a[4][4], uint32_t b[4][2]) {
        #pragma unroll
        for (int mt = 0; mt < 4; ++mt)
            #pragma unroll
            for (int nj = 0; nj < 4; ++nj)
                mma_fp8(c[mt][nj], a[mt], b[nj]);
    };

    const int KT = K >> 6;
    load_stage(0, 0);
    load_stage(1, 1);
    load_stage(2, 2);
    int buf = 0;
    for (int kt = 0; kt < KT; ++kt) {
        if (kt + 3 < KT) {
            int nb = buf + 3; if (nb >= NSTAGE) nb -= NSTAGE;
            load_stage(kt + 3, nb);
            CP_WAIT(3);
        } else if (kt + 2 < KT) { CP_WAIT(2); }
        else if (kt + 1 < KT)   { CP_WAIT(1); }
        else                    { CP_WAIT(0); }
        __syncthreads();

        uint32_t base = sb + buf * STAGE_SZ;
        uint32_t a0[4][4], b0[4][2], a1[4][4], b1[4][2];
        load_frags(base, 0, a0, b0);
        load_frags(base, 1, a1, b1);
        do_mmas(a0, b0);
        do_mmas(a1, b1);
        __syncthreads();
        if (++buf == NSTAGE) buf = 0;
    }

    #pragma unroll
    for (int mt = 0; mt < 4; ++mt) {
        #pragma unroll
        for (int nj = 0; nj < 4; ++nj) {
            int row0 = bm + wm * 64 + mt * 16 + (lane >> 2);
            int col  = bn + wn * 32 + nj * 8 + (lane & 3) * 2;
            float b0 = bias[col], b1 = bias[col + 1];
            long p0 = (long)row0 * N + col, p1 = (long)(row0 + 8) * N + col;
            float r0 = (EPI == EPI_RESID) ? resid[p0]     : 0.f;
            float r1 = (EPI == EPI_RESID) ? resid[p0 + 1] : 0.f;
            float r2 = (EPI == EPI_RESID) ? resid[p1]     : 0.f;
            float r3 = (EPI == EPI_RESID) ? resid[p1 + 1] : 0.f;
            float v0 = epi_apply(EPI, c[mt][nj][0] * WINV + b0, r0);
            float v1 = epi_apply(EPI, c[mt][nj][1] * WINV + b1, r1);
            float v2 = epi_apply(EPI, c[mt][nj][2] * WINV + b0, r2);
            float v3 = epi_apply(EPI, c[mt][nj][3] * WINV + b1, r3);
            *(float2*)(C + p0) = make_float2(v0, v1);
            *(float2*)(C + p1) = make_float2(v2, v3);
        }
    }
}

// ---------------------------------------------------------------------------
// gemm_fp8_n64: block 128x64, 8 warps (4m x 2n), warp tile 32x32. For the
// N=1024 out_proj: grid (16,16)=256 CTAs -> full single wave at 2 CTA/SM.
// ---------------------------------------------------------------------------
#define STAGE64   ((128 + 64) * ROWB)       // 15360 B
#define GEMM64_SMEM (NSTAGE * STAGE64)      // 61440 B

template<int EPI>
__global__ __launch_bounds__(256, 2)
void gemm_fp8_n64(const __nv_fp8_e4m3* __restrict__ A, const __nv_fp8_e4m3* __restrict__ B,
                  const float* __restrict__ bias, const float* __restrict__ resid,
                  float* __restrict__ C, int M, int N, int K) {
    extern __shared__ char smem[];
    uint32_t sb = smem_to_u32(smem);
    int tid  = threadIdx.x;
    int lane = tid & 31;
    int wid  = tid >> 5;
    int wm   = wid & 3;                    // 4 m-groups of 32
    int wn   = wid >> 2;                   // 2 n-groups of 32
    int bm = blockIdx.y * 128, bn = blockIdx.x * 64;

    const __nv_fp8_e4m3* Abase = A + (long)bm * K;
    const __nv_fp8_e4m3* Bbase = B + (long)bn * K;

    // 3 chunks of 16B per thread per stage (768 chunks total)
    uint32_t s_off[3];
    const __nv_fp8_e4m3* s_src[3];
    #pragma unroll
    for (int i = 0; i < 3; ++i) {
        int id = tid + i * 256;            // 0..767
        if (id < 512) {
            int row = id >> 2, c = id & 3;
            s_off[i] = (uint32_t)(row * ROWB + c * 16);
            s_src[i] = Abase + (long)row * K + c * 16;
        } else {
            int rem = id - 512;
            int row = rem >> 2, c = rem & 3;
            s_off[i] = (uint32_t)(128 * ROWB + row * ROWB + c * 16);
            s_src[i] = Bbase + (long)row * K + c * 16;
        }
    }

    auto load_stage = [&](int kt, int buf) {
        uint32_t base = sb + buf * STAGE64;
        #pragma unroll
        for (int i = 0; i < 3; ++i)
            CP_ASYNC16(base + s_off[i], s_src[i] + kt * 64);
        CP_COMMIT();
    };

    float c[2][4][4];
    #pragma unroll
    for (int mt = 0; mt < 2; ++mt)
        #pragma unroll
        for (int nj = 0; nj < 4; ++nj)
            #pragma unroll
            for (int r = 0; r < 4; ++r) c[mt][nj][r] = 0.f;

    int a_row = wm * 32 + (lane & 15);
    int a_kb  = (lane >> 4) << 4;
    int b_row = wn * 32 + ((lane >> 4) << 3) + (lane & 7);
    int b_kb  = ((lane >> 3) & 1) << 4;

    auto load_frags = [&](uint32_t base, int ks, uint32_t a[2][4], uint32_t b[4][2]) {
        uint32_t kboff = ks * 32;
        #pragma unroll
        for (int mt = 0; mt < 2; ++mt) {
            uint32_t off = (uint32_t)((a_row + mt * 16) * ROWB) + a_kb + kboff;
            ldsm_x4(a[mt], base + off);
        }
        #pragma unroll
        for (int nt = 0; nt < 2; ++nt) {
            uint32_t off = (uint32_t)((b_row + nt * 16) * ROWB) + b_kb + kboff;
            uint32_t t0[4];
            ldsm_x4(t0, base + 128 * ROWB + off);
            b[nt*2][0]   = t0[0]; b[nt*2][1]   = t0[1];
            b[nt*2+1][0] = t0[2]; b[nt*2+1][1] = t0[3];
        }
    };
    auto do_mmas = [&](uint32_t a[2][4], uint32_t b[4][2]) {
        #pragma unroll
        for (int mt = 0; mt < 2; ++mt)
            #pragma unroll
            for (int nj = 0; nj < 4; ++nj)
                mma_fp8(c[mt][nj], a[mt], b[nj]);
    };

    const int KT = K >> 6;
    load_stage(0, 0);
    load_stage(1, 1);
    load_stage(2, 2);
    int buf = 0;
    for (int kt = 0; kt < KT; ++kt) {
        if (kt + 3 < KT) {
            int nb = buf + 3; if (nb >= NSTAGE) nb -= NSTAGE;
            load_stage(kt + 3, nb);
            CP_WAIT(3);
        } else if (kt + 2 < KT) { CP_WAIT(2); }
        else if (kt + 1 < KT)   { CP_WAIT(1); }
        else                    { CP_WAIT(0); }
        __syncthreads();

        uint32_t base = sb + buf * STAGE64;
        uint32_t a0[2][4], b0[4][2], a1[2][4], b1[4][2];
        load_frags(base, 0, a0, b0);
        load_frags(base, 1, a1, b1);
        do_mmas(a0, b0);
        do_mmas(a1, b1);
        __syncthreads();
        if (++buf == NSTAGE) buf = 0;
    }

    #pragma unroll
    for (int mt = 0; mt < 2; ++mt) {
        #pragma unroll
        for (int nj = 0; nj < 4; ++nj) {
            int row0 = bm + wm * 32 + mt * 16 + (lane >> 2);
            int col  = bn + wn * 32 + nj * 8 + (lane & 3) * 2;
            float b0 = bias[col], b1 = bias[col + 1];
            long p0 = (long)row0 * N + col, p1 = (long)(row0 + 8) * N + col;
            float r0 = (EPI == EPI_RESID) ? resid[p0]     : 0.f;
            float r1 = (EPI == EPI_RESID) ? resid[p0 + 1] : 0.f;
            float r2 = (EPI == EPI_RESID) ? resid[p1]     : 0.f;
            float r3 = (EPI == EPI_RESID) ? resid[p1 + 1] : 0.f;
            float v0 = epi_apply(EPI, c[mt][nj][0] * WINV + b0, r0);
            float v1 = epi_apply(EPI, c[mt][nj][1] * WINV + b1, r1);
            float v2 = epi_apply(EPI, c[mt][nj][2] * WINV + b0, r2);
            float v3 = epi_apply(EPI, c[mt][nj][3] * WINV + b1, r3);
            *(float2*)(C + p0) = make_float2(v0, v1);
            *(float2*)(C + p1) = make_float2(v2, v3);
        }
    }
}

// ---------------------------------------------------------------------------
// x_proj fused with causal conv(4)+SiLU. Grid (8 kchunks, 64 rowtiles).
// ---------------------------------------------------------------------------
#define XP_KCHUNK 256
__global__ __launch_bounds__(256)
void xproj_conv_kernel(const float* __restrict__ W,
                       const float* __restrict__ conv_w,
                       const float* __restrict__ conv_b) {
    __shared__ float Xs[32][65];
    __shared__ float Ws[32][65];
    __shared__ float Cw[XP_KCHUNK][4];
    __shared__ float Cb[XP_KCHUNK];
    int tid = threadIdx.x;
    int kbase = blockIdx.x * XP_KCHUNK;
    int row0  = blockIdx.y * 32;
    if (tid < XP_KCHUNK) {
        float4 w = *(const float4*)(conv_w + (long)(kbase + tid) * 4);
        Cw[tid][0] = w.x; Cw[tid][1] = w.y; Cw[tid][2] = w.z; Cw[tid][3] = w.w;
        Cb[tid] = conv_b[kbase + tid];
    }
    __syncthreads();

    int rg = (tid >> 5) * 4;
    int n  = tid & 31;
    float acc[4] = {0.f, 0.f, 0.f, 0.f};
    for (int k0 = kbase; k0 < kbase + XP_KCHUNK; k0 += 64) {
        #pragma unroll
        for (int i = 0; i < 2; ++i) {
            int id = tid * 2 + i;
            int r = id >> 4, c4 = (id & 15) * 4;
            int row = row0 + r;
            int t = row & (LSEQ - 1);
            const float* xp = g_xz + (long)row * (2 * DINNER) + k0 + c4;
            float4 zf = make_float4(0.f, 0.f, 0.f, 0.f);
            float4 v3 = *(const float4*)xp;
            float4 v2 = (t >= 1) ? *(const float4*)(xp - 1 * 2 * DINNER) : zf;
            float4 v1 = (t >= 2) ? *(const float4*)(xp - 2 * 2 * DINNER) : zf;
            float4 v0 = (t >= 3) ? *(const float4*)(xp - 3 * 2 * DINNER) : zf;
            int ci = k0 + c4 - kbase;
            float o[4];
            o[0] = Cb[ci+0] + v0.x*Cw[ci+0][0] + v1.x*Cw[ci+0][1] + v2.x*Cw[ci+0][2] + v3.x*Cw[ci+0][3];
            o[1] = Cb[ci+1] + v0.y*Cw[ci+1][0] + v1.y*Cw[ci+1][1] + v2.y*Cw[ci+1][2] + v3.y*Cw[ci+1][3];
            o[2] = Cb[ci+2] + v0.z*Cw[ci+2][0] + v1.z*Cw[ci+2][1] + v2.z*Cw[ci+2][2] + v3.z*Cw[ci+2][3];
            o[3] = Cb[ci+3] + v0.w*Cw[ci+3][0] + v1.w*Cw[ci+3][1] + v2.w*Cw[ci+3][2] + v3.w*Cw[ci+3][3];
            #pragma unroll
            for (int k = 0; k < 4; ++k) {
                o[k] = o[k] / (1.0f + expf(-o[k]));     // silu
                Xs[r][c4 + k] = o[k];
            }
            *(uint32_t*)(g_xc_f8 + (long)row * DINNER + k0 + c4) =
                pack_fp8x4(o[0], o[1], o[2], o[3]);
            float4 wv = *(const float4*)(W + (long)r * DINNER + k0 + c4);
            Ws[r][c4] = wv.x; Ws[r][c4+1] = wv.y; Ws[r][c4+2] = wv.z; Ws[r][c4+3] = wv.w;
        }
        __syncthreads();
        #pragma unroll
        for (int kk = 0; kk < 64; ++kk) {
            float w = Ws[n][kk];
            #pragma unroll
            for (int i = 0; i < 4; ++i) acc[i] = fmaf(Xs[rg + i][kk], w, acc[i]);
        }
        __syncthreads();
    }
    int off = (n & 15) * 2 + (n >> 4);
    #pragma unroll
    for (int i = 0; i < 4; ++i)
        atomicAdd(&g_bc[(long)(row0 + rg + i) * 32 + off], acc[i]);
}

// ---------------------------------------------------------------------------
// Fused chunked selective scan (3 phases in one kernel); xc fp8, y fp8.
// ---------------------------------------------------------------------------
#define CH_STRIDE 1032
#define SC_SMEM  (2 * 8 * CH_STRIDE * 4)

__global__ __launch_bounds__(512, 2)
void scan_fused(const float* __restrict__ A_log, const float* __restrict__ Dvec) {
    extern __shared__ float sm[];
    float* s_ap = sm;
    float* s_hd = sm + 8 * CH_STRIDE;

    int tid  = threadIdx.x;
    int wid  = tid >> 5;
    int lane = tid & 31;
    int chl  = lane >> 2;
    int sg   = lane & 3;
    int s0   = sg * 4;
    int pair = blockIdx.x * 8 + chl;
    int b = pair >> 11;
    int c = pair & (DINNER - 1);

    float a[4];
    #pragma unroll
    for (int k = 0; k < 4; ++k) a[k] = -expf(A_log[c * DSTATE + s0 + k]);
    float Dc = Dvec[c];

    const float* dl  = g_delta + (long)b * LSEQ * DINNER + c;
    const __nv_fp8_e4m3* xcb = g_xc_f8 + (long)b * LSEQ * DINNER + c;
    const float* bcb = g_bc + (long)b * LSEQ * 32 + s0 * 2;
    const float* zb  = g_xz + (long)b * LSEQ * 2 * DINNER + DINNER + c;
    __nv_fp8_e4m3* yb = g_y_f8 + (long)b * LSEQ * DINNER + c;

    // phase 1
    for (int sgm = wid * 4; sgm < wid * 4 + 4; ++sgm) {
        float h[4] = {0.f, 0.f, 0.f, 0.f};
        float ap[4] = {1.f, 1.f, 1.f, 1.f};
        int tb = sgm * SEGLEN;
        #pragma unroll
        for (int j = 0; j < SEGLEN; ++j) {
            int t = tb + j;
            float  d   = dl [(long)t * DINNER];
            float  xv  = float(xcb[(long)t * DINNER]);
            float4 bc0 = *(const float4*)(bcb + t * 32);
            float4 bc1 = *(const float4*)(bcb + t * 32 + 4);
            float dx = d * xv;
            float da0 = __expf(fmaxf(d * a[0], -10.f));
            float da1 = __expf(fmaxf(d * a[1], -10.f));
            float da2 = __expf(fmaxf(d * a[2], -10.f));
            float da3 = __expf(fmaxf(d * a[3], -10.f));
            h[0] = fmaf(da0, h[0], dx * bc0.x);  ap[0] *= da0;
            h[1] = fmaf(da1, h[1], dx * bc0.z);  ap[1] *= da1;
            h[2] = fmaf(da2, h[2], dx * bc1.x);  ap[2] *= da2;
            h[3] = fmaf(da3, h[3], dx * bc1.z);  ap[3] *= da3;
        }
        int si = chl * CH_STRIDE + sgm * 16 + s0;
        *(float4*)(s_hd + si) = make_float4(h[0], h[1], h[2], h[3]);
        *(float4*)(s_ap + si) = make_float4(ap[0], ap[1], ap[2], ap[3]);
    }
    __syncthreads();

    // phase 2
    if (wid < 4) {
        int s  = lane & 15;
        int lp = wid * 2 + (lane >> 4);
        float h = 0.f;
        for (int g = 0; g < NSEG; ++g) {
            int idx = lp * CH_STRIDE + g * 16 + s;
            float ap_ = s_ap[idx];
            float hd_ = s_hd[idx];
            s_ap[idx] = h;
            h = fmaf(ap_, h, hd_);
            float ss = h * h;
            ss += __shfl_xor_sync(0xffffffffu, ss, 8);
            ss += __shfl_xor_sync(0xffffffffu, ss, 4);
            ss += __shfl_xor_sync(0xffffffffu, ss, 2);
            ss += __shfl_xor_sync(0xffffffffu, ss, 1);
            if (ss > 100.0f) h *= 10.0f * rsqrtf(ss);
        }
    }
    __syncthreads();

    // phase 3
    for (int sgm = wid * 4; sgm < wid * 4 + 4; ++sgm) {
        float4 hs = *(const float4*)(s_ap + chl * CH_STRIDE + sgm * 16 + s0);
        float h[4] = { hs.x, hs.y, hs.z, hs.w };
        int tb = sgm * SEGLEN;
        #pragma unroll
        for (int j = 0; j < SEGLEN; ++j) {
            int t = tb + j;
            float  d   = dl [(long)t * DINNER];
            float  xv  = float(xcb[(long)t * DINNER]);
            float4 bc0 = *(const float4*)(bcb + t * 32);
            float4 bc1 = *(const float4*)(bcb + t * 32 + 4);
            float  z   = zb [(long)t * 2 * DINNER];
            float dx = d * xv;
            float da0 = __expf(fmaxf(d * a[0], -10.f));
            float da1 = __expf(fmaxf(d * a[1], -10.f));
            float da2 = __expf(fmaxf(d * a[2], -10.f));
            float da3 = __expf(fmaxf(d * a[3], -10.f));
            h[0] = fmaf(da0, h[0], dx * bc0.x);
            h[1] = fmaf(da1, h[1], dx * bc0.z);
            h[2] = fmaf(da2, h[2], dx * bc1.x);
            h[3] = fmaf(da3, h[3], dx * bc1.z);
            if (j == SEGLEN - 1) {
                float ss = h[0]*h[0] + h[1]*h[1] + h[2]*h[2] + h[3]*h[3];
                ss += __shfl_xor_sync(0xffffffffu, ss, 1);
                ss += __shfl_xor_sync(0xffffffffu, ss, 2);
                if (ss > 100.0f) {
                    float r = 10.0f * rsqrtf(ss);
                    h[0] *= r; h[1] *= r; h[2] *= r; h[3] *= r;
                }
            }
            float p = h[0]*bc0.y + h[1]*bc0.w + h[2]*bc1.y + h[3]*bc1.w;
            p += __shfl_xor_sync(0xffffffffu, p, 1);
            p += __shfl_xor_sync(0xffffffffu, p, 2);
            if (sg == 0) {
                float yv = p + Dc * xv;
                yv *= z / (1.0f + __expf(-z));
                yb[(long)t * DINNER] = __nv_fp8_e4m3(yv);
            }
        }
    }
}

// ---------------------------------------------------------------------------
// Launch (7 kernels)
// ---------------------------------------------------------------------------
extern "C" void kernel_launch(void* const* d_in, const int* in_sizes, int n_in,
                              void* d_out, int out_size) {
    const float* x             = (const float*)d_in[0];
    const float* in_proj_w     = (const float*)d_in[1];
    const float* in_proj_b     = (const float*)d_in[2];
    const float* conv_w        = (const float*)d_in[3];
    const float* conv_b        = (const float*)d_in[4];
    const float* x_proj_w      = (const float*)d_in[5];
    const float* x_proj_b      = (const float*)d_in[6];
    const float* dt_proj_w     = (const float*)d_in[7];
    const float* dt_proj_b     = (const float*)d_in[8];
    const float* A_log         = (const float*)d_in[9];
    const float* Dvec          = (const float*)d_in[10];
    const float* out_proj_w    = (const float*)d_in[11];
    const float* out_proj_b    = (const float*)d_in[12];
    const float* in_norm_alpha = (const float*)d_in[13];
    const float* in_norm_bias  = (const float*)d_in[14];
    const float* norm_alpha    = (const float*)d_in[15];
    const float* norm_bias     = (const float*)d_in[16];
    float* out = (float*)d_out;

    __nv_fp8_e4m3 *xn_f, *wi_f, *wd_f, *wo_f, *xc_f, *y_f;
    float *xz, *delta, *obuf;
    cudaGetSymbolAddress((void**)&xn_f, g_xn_f8);
    cudaGetSymbolAddress((void**)&wi_f, g_wi_f8);
    cudaGetSymbolAddress((void**)&wd_f, g_wd_f8);
    cudaGetSymbolAddress((void**)&wo_f, g_wo_f8);
    cudaGetSymbolAddress((void**)&xc_f, g_xc_f8);
    cudaGetSymbolAddress((void**)&y_f,  g_y_f8);
    cudaGetSymbolAddress((void**)&xz,    g_xz);
    cudaGetSymbolAddress((void**)&delta, g_delta);
    cudaGetSymbolAddress((void**)&obuf,  g_out);

    cudaFuncSetAttribute(gemm_fp8<EPI_BIAS>,      cudaFuncAttributeMaxDynamicSharedMemorySize, GEMM_SMEM);
    cudaFuncSetAttribute(gemm_fp8<EPI_SOFTPLUS>,  cudaFuncAttributeMaxDynamicSharedMemorySize, GEMM_SMEM);
    cudaFuncSetAttribute(gemm_fp8_n64<EPI_RESID>, cudaFuncAttributeMaxDynamicSharedMemorySize, GEMM64_SMEM);
    cudaFuncSetAttribute(scan_fused,              cudaFuncAttributeMaxDynamicSharedMemorySize, SC_SMEM);

    // 0. fused: input LN (fp8 out) + weight converts (x64 -> fp8) + bc seed
    ln_cvt_kernel<<<ROWS + CVT_BLOCKS + BC_BLOCKS, 256>>>(
        x, in_norm_alpha, in_norm_bias,
        in_proj_w, dt_proj_w, out_proj_w, x_proj_b);
    // 1. in_proj (2048 x 4096 x 1024) fp8
    gemm_fp8<EPI_BIAS><<<dim3(32, 16), 256, GEMM_SMEM>>>(
        xn_f, wi_f, in_proj_b, nullptr, xz, ROWS, 2 * DINNER, DMODEL);
    // 2. conv+silu fused into x_proj (K-parallel, atomic accumulate)
    xproj_conv_kernel<<<dim3(DINNER / XP_KCHUNK, ROWS / 32), 256>>>(
        x_proj_w, conv_w, conv_b);
    // 3. dt_proj + softplus + clip fp8
    gemm_fp8<EPI_SOFTPLUS><<<dim3(16, 16), 256, GEMM_SMEM>>>(
        xc_f, wd_f, dt_proj_b, nullptr, delta, ROWS, DINNER, DINNER);
    // 4. fused 3-phase selective scan + z gate
    scan_fused<<<512, 512, SC_SMEM>>>(A_log, Dvec);
    // 5. out_proj + residual (2048 x 1024 x 2048), 128x64 tiles -> 256 CTAs
    gemm_fp8_n64<EPI_RESID><<<dim3(16, 16), 256, GEMM64_SMEM>>>(
        y_f, wo_f, out_proj_b, x, obuf, ROWS, DMODEL, DINNER);
    // 6. final layernorm -> d_out
    ln_out_kernel<<<ROWS, 256>>>(obuf, norm_alpha, norm_bias, out);
}